// round 1
// baseline (speedup 1.0000x reference)
#include <cuda_runtime.h>
#include <math.h>

#define B 4
#define C 192
#define NN 160
#define MM 160
#define HEADS 4
#define DH 32
#define HID 128
#define NMEM 4
#define SQRTC 13.856406460551018f   /* sqrt(192) */
#define SCALE 0.17677669529663687f  /* 32^-0.5 */

// ---------------- scratch (device globals; no allocation allowed) ----------
__device__ float g_w[B*NN*MM];          // sqrt(C)/max(||x[b,:,n,m]||,eps)
__device__ float g_rowft[B*C*NN];       // mean over m
__device__ float g_colft[B*C*MM];       // mean over n
__device__ float g_vbr[B*C*MM];         // gv[c] * sum_n x*w   (V-bar for row attn, index m)
__device__ float g_vbc[B*C*NN];         // gv[c] * sum_m x*w   (V-bar for col attn, index n)
__device__ float g_nrow[B*NN];          // ||row_ft[b,:,n]||
__device__ float g_ncol[B*MM];          // ||col_ft[b,:,m]||
__device__ float g_q [2][B*HEADS*160*DH];
__device__ float g_k [2][B*HEADS*160*DH];
__device__ float g_vs[2][B*HEADS*160*DH];
__device__ float g_ho[2][B*HEADS*160*DH];
__device__ float g_attn[2][B*C*160];    // row_attn / col_attn (b,c,pos)

// ---------------- K1: per-pixel channel norms -> w --------------------------
__global__ void k_norm(const float* __restrict__ x) {
    int b = blockIdx.x / NN, n = blockIdx.x % NN, m = threadIdx.x;
    const float* xp = x + ((size_t)b*C*NN + n)*MM + m;
    float ss = 0.f;
    #pragma unroll 4
    for (int c = 0; c < C; c++) { float v = xp[(size_t)c*NN*MM]; ss += v*v; }
    g_w[(b*NN + n)*MM + m] = SQRTC / fmaxf(sqrtf(ss), 1e-12f);
}

// ---------------- K2: one pass over x -> row_ft, col_ft, vbr, vbc ----------
__global__ void k_reduce(const float* __restrict__ x, const float* __restrict__ gv) {
    int b = blockIdx.x / C, c = blockIdx.x % C;
    int lane = threadIdx.x & 31, warp = threadIdx.x >> 5;   // 5 warps
    const float* xp = x + ((size_t)(b*C + c))*NN*MM;
    const float* wp = g_w + b*NN*MM;
    float gvc = gv[c];
    float colp[5] = {0,0,0,0,0}, vrp[5] = {0,0,0,0,0};
    for (int i = 0; i < 32; i++) {
        int n = warp*32 + i;
        float rs = 0.f, vcs = 0.f;
        #pragma unroll
        for (int mc = 0; mc < 5; mc++) {
            int m = mc*32 + lane;
            float v  = xp[n*MM + m];
            float wv = wp[n*MM + m];
            rs += v; vcs += v*wv;
            colp[mc] += v; vrp[mc] += v*wv;
        }
        #pragma unroll
        for (int o = 16; o; o >>= 1) {
            rs  += __shfl_xor_sync(0xffffffffu, rs,  o);
            vcs += __shfl_xor_sync(0xffffffffu, vcs, o);
        }
        if (!lane) {
            g_rowft[(b*C + c)*NN + n] = rs * (1.0f/MM);
            g_vbc  [(b*C + c)*NN + n] = gvc * vcs;
        }
    }
    __shared__ float scol[5][160], svr[5][160];
    #pragma unroll
    for (int mc = 0; mc < 5; mc++) {
        scol[warp][mc*32 + lane] = colp[mc];
        svr [warp][mc*32 + lane] = vrp[mc];
    }
    __syncthreads();
    int m = threadIdx.x;
    float cs = 0.f, vr = 0.f;
    #pragma unroll
    for (int w2 = 0; w2 < 5; w2++) { cs += scol[w2][m]; vr += svr[w2][m]; }
    g_colft[(b*C + c)*MM + m] = cs * (1.0f/NN);
    g_vbr  [(b*C + c)*MM + m] = gvc * vr;
}

// ---------------- K3: channel norms of row_ft / col_ft ---------------------
__global__ void k_ftnorm() {
    int which = blockIdx.x >> 2, b = blockIdx.x & 3;
    const float* src = which ? g_colft : g_rowft;
    float* dst = which ? g_ncol : g_nrow;
    int t = threadIdx.x;
    float ss = 0.f;
    #pragma unroll 4
    for (int c = 0; c < C; c++) { float v = src[(b*C + c)*160 + t]; ss += v*v; }
    dst[b*160 + t] = sqrtf(ss);
}

// ---------------- K4: six (128 x 640, K=192) projections --------------------
// which: 0=Q_row 1=K_row 2=V_row 3=Q_col 4=K_col 5=V_col. SCALE folded into Q.
__global__ void k_proj(const float* __restrict__ Wq, const float* __restrict__ Wk,
                       const float* __restrict__ Wv, const float* __restrict__ gq,
                       const float* __restrict__ gk) {
    int which = blockIdx.y;
    int p0 = blockIdx.x * 16;
    int b = p0 / 160, q0 = p0 % 160;
    const float *src, *W, *gvec = 0, *nrm = 0;
    float* out; float extra = 1.f;
    switch (which) {
        case 0: src=g_rowft; W=Wq; gvec=gq; nrm=g_nrow; out=g_q[0];  extra=SCALE; break;
        case 1: src=g_colft; W=Wk; gvec=gk; nrm=g_ncol; out=g_k[0];  break;
        case 2: src=g_vbr;   W=Wv;                       out=g_vs[0]; break;
        case 3: src=g_colft; W=Wq; gvec=gq; nrm=g_ncol; out=g_q[1];  extra=SCALE; break;
        case 4: src=g_rowft; W=Wk; gvec=gk; nrm=g_nrow; out=g_k[1];  break;
        default:src=g_vbc;   W=Wv;                       out=g_vs[1]; break;
    }
    __shared__ float Xs[C][16];
    __shared__ float Wsm[128][33];
    __shared__ float fs[16];
    if (threadIdx.x < 16)
        fs[threadIdx.x] = gvec ? extra * SQRTC / fmaxf(nrm[b*160 + q0 + threadIdx.x], 1e-12f)
                               : 1.f;
    __syncthreads();
    for (int idx = threadIdx.x; idx < C*16; idx += 128) {
        int c = idx >> 4, pp = idx & 15;
        float v = src[(b*C + c)*160 + q0 + pp] * fs[pp];
        if (gvec) v *= gvec[c];
        Xs[c][pp] = v;
    }
    float acc[16];
    #pragma unroll
    for (int p = 0; p < 16; p++) acc[p] = 0.f;
    for (int c0 = 0; c0 < C; c0 += 32) {
        __syncthreads();
        for (int idx = threadIdx.x; idx < 128*32; idx += 128) {
            int r = idx >> 5, cc = idx & 31;
            Wsm[r][cc] = W[r*C + c0 + cc];
        }
        __syncthreads();
        for (int cc = 0; cc < 32; cc++) {
            float wv = Wsm[threadIdx.x][cc];
            #pragma unroll
            for (int p = 0; p < 16; p++) acc[p] += wv * Xs[c0 + cc][p];
        }
    }
    int h = threadIdx.x >> 5, dd = threadIdx.x & 31;
    #pragma unroll
    for (int p = 0; p < 16; p++)
        out[((b*HEADS + h)*160 + q0 + p)*DH + dd] = acc[p];
}

// ---------------- K5: attention with memory KV ------------------------------
// grid (qtile=5, bh=16, axial=2), 256 threads. Rows 160..163 = memory slots.
__global__ void k_attn(const float* __restrict__ memkv) {
    int axial = blockIdx.z, bh = blockIdx.y, qt = blockIdx.x;
    int h = bh & 3;
    const float* Q = g_q [axial] + (bh*160 + qt*32)*DH;
    const float* K = g_k [axial] + bh*160*DH;
    const float* V = g_vs[axial] + bh*160*DH;
    float* out     = g_ho[axial] + (bh*160 + qt*32)*DH;
    __shared__ float Ks[164][33];
    __shared__ float Qs[32][33];
    __shared__ float S [32][168];
    __shared__ float invZ[32];
    int tid = threadIdx.x;
    for (int idx = tid; idx < 160*32; idx += 256) Ks[idx >> 5][idx & 31] = K[idx];
    for (int idx = tid; idx < 4*32;   idx += 256) {
        int j = idx >> 5, d = idx & 31;
        Ks[160 + j][d] = memkv[(h*NMEM + j)*DH + d];
    }
    for (int idx = tid; idx < 32*32; idx += 256) Qs[idx >> 5][idx & 31] = Q[idx];
    __syncthreads();
    for (int idx = tid; idx < 32*164; idx += 256) {
        int qi = idx / 164, k = idx - qi*164;
        float s = 0.f;
        #pragma unroll
        for (int d = 0; d < 32; d++) s += Qs[qi][d] * Ks[k][d];
        S[qi][k] = s;
    }
    __syncthreads();
    int warp = tid >> 5, lane = tid & 31;
    for (int qi = warp; qi < 32; qi += 8) {
        float mx = -1e30f;
        for (int k = lane; k < 164; k += 32) mx = fmaxf(mx, S[qi][k]);
        #pragma unroll
        for (int o = 16; o; o >>= 1) mx = fmaxf(mx, __shfl_xor_sync(0xffffffffu, mx, o));
        float z = 0.f;
        for (int k = lane; k < 164; k += 32) {
            float e = __expf(S[qi][k] - mx);
            S[qi][k] = e;
            z += (k < 160 ? 160.0f : 1.0f) * e;   // rep = N = M = 160
        }
        #pragma unroll
        for (int o = 16; o; o >>= 1) z += __shfl_xor_sync(0xffffffffu, z, o);
        if (!lane) invZ[qi] = 1.0f / z;
    }
    __syncthreads();
    int d = tid & 31, q0 = tid >> 5;
    float acc[4] = {0.f, 0.f, 0.f, 0.f};
    for (int k = 0; k < 160; k++) {
        float vv = V[k*DH + d];
        #pragma unroll
        for (int i = 0; i < 4; i++) acc[i] += S[q0 + 8*i][k] * vv;
    }
    const float* memv = memkv + HEADS*NMEM*DH;
    #pragma unroll
    for (int j = 0; j < 4; j++) {
        float vv = memv[(h*NMEM + j)*DH + d];
        #pragma unroll
        for (int i = 0; i < 4; i++) acc[i] += S[q0 + 8*i][160 + j] * vv;
    }
    #pragma unroll
    for (int i = 0; i < 4; i++) {
        int qi = q0 + 8*i;
        out[qi*DH + d] = acc[i] * invZ[qi];
    }
}

// ---------------- K6: output projection Wo + bo ------------------------------
__global__ void k_wo(const float* __restrict__ Wo, const float* __restrict__ bo) {
    int axial = blockIdx.y;
    int p0 = blockIdx.x * 16;
    int b = p0 / 160, q0 = p0 % 160;
    const float* ho = g_ho[axial];
    __shared__ float Xs[HID][17];
    for (int idx = threadIdx.x; idx < HID*16; idx += 192) {
        int pp = idx >> 7, hd = idx & 127;
        int h = hd >> 5, d = hd & 31;
        Xs[hd][pp] = ho[((b*HEADS + h)*160 + q0 + pp)*DH + d];
    }
    __syncthreads();
    int c = threadIdx.x;   // 192
    float acc[16];
    #pragma unroll
    for (int p = 0; p < 16; p++) acc[p] = 0.f;
    for (int hd = 0; hd < HID; hd++) {
        float wv = Wo[c*HID + hd];
        #pragma unroll
        for (int p = 0; p < 16; p++) acc[p] += wv * Xs[hd][p];
    }
    float bb = bo[c];
    #pragma unroll
    for (int p = 0; p < 16; p++)
        g_attn[axial][(b*C + c)*160 + q0 + p] = acc[p] + bb;
}

// ---------------- K7: fused Wr GEMMs + broadcast add epilogue ---------------
__global__ void k_final(const float* __restrict__ Wr, float* __restrict__ out) {
    int b = blockIdx.x / C, d = blockIdx.x % C;
    int t = threadIdx.x;   // 160
    const float* ra = g_attn[0] + b*C*160;
    const float* ca = g_attn[1] + b*C*160;
    const float* w1 = Wr + (size_t)d*2*C;
    float racc = 0.f, cacc = 0.f;
    #pragma unroll 4
    for (int c = 0; c < C; c++) {
        racc += w1[c]     * ra[c*160 + t];
        cacc += w1[C + c] * ca[c*160 + t];
    }
    __shared__ float Rs[160], Cs[160];
    Rs[t] = racc; Cs[t] = cacc;
    __syncthreads();
    float cv = Cs[t];
    float* op = out + ((size_t)(b*C + d)*NN)*MM + t;
    for (int n = 0; n < NN; n++) op[n*MM] = Rs[n] + cv;
}

// ---------------- launch -----------------------------------------------------
extern "C" void kernel_launch(void* const* d_in, const int* in_sizes, int n_in,
                              void* d_out, int out_size) {
    const float* x     = (const float*)d_in[0];
    const float* gq    = (const float*)d_in[1];
    const float* gk    = (const float*)d_in[2];
    const float* gv    = (const float*)d_in[3];
    const float* Wq    = (const float*)d_in[4];
    const float* Wk    = (const float*)d_in[5];
    const float* Wv    = (const float*)d_in[6];
    const float* memkv = (const float*)d_in[7];
    const float* Wo    = (const float*)d_in[8];
    const float* bo    = (const float*)d_in[9];
    const float* Wr    = (const float*)d_in[10];
    float* out = (float*)d_out;

    k_norm  <<<B*NN, 160>>>(x);
    k_reduce<<<B*C, 160>>>(x, gv);
    k_ftnorm<<<8, 160>>>();
    k_proj  <<<dim3(40, 6), 128>>>(Wq, Wk, Wv, gq, gk);
    k_attn  <<<dim3(5, 16, 2), 256>>>(memkv);
    k_wo    <<<dim3(40, 2), 192>>>(Wo, bo);
    k_final <<<B*C, 160>>>(Wr, out);
}

// round 2
// speedup vs baseline: 1.2470x; 1.2470x over previous
#include <cuda_runtime.h>
#include <math.h>

#define B 4
#define C 192
#define HEADS 4
#define DH 32
#define HID 128
#define NMEM 4
#define SQRTC 13.856406460551018f   /* sqrt(192) */
#define SCALE 0.17677669529663687f  /* 32^-0.5 */

// ---------------- scratch (device globals) ----------------------------------
__device__ float g_w[B*160*160];        // sqrt(C)/max(||x[b,:,n,m]||,eps)
__device__ float g_rowft[B*C*160];      // mean over m
__device__ float g_colft[B*C*160];      // mean over n
__device__ float g_vbr[B*C*160];        // gv[c]*sum_n x*w (row-attn V, index m)
__device__ float g_vbc[B*C*160];        // gv[c]*sum_m x*w (col-attn V, index n)
__device__ float g_q [2][B*HEADS*160*DH];
__device__ float g_k [2][B*HEADS*160*DH];
__device__ float g_vs[2][B*HEADS*160*DH];
__device__ float g_hoT[2][B*HID*160];   // transposed: [(b*128+hid)*160 + pos]
__device__ float g_E[2][C*HID];         // Wr{1,2} @ Wo
__device__ float g_e[2][C];             // Wr{1,2} @ bo

// ---------------- K0: fold Wr @ Wo, Wr @ bo ---------------------------------
__global__ void k_fold(const float* __restrict__ Wr, const float* __restrict__ Wo,
                       const float* __restrict__ bo) {
    int ax = blockIdx.x, d0 = blockIdx.y * 8;
    __shared__ float Wrs[8][192];
    int t = threadIdx.x;  // 128
    for (int idx = t; idx < 8*192; idx += 128) {
        int j = idx / 192, c = idx % 192;
        Wrs[j][c] = Wr[(d0 + j)*2*C + ax*C + c];
    }
    __syncthreads();
    float acc[8] = {0,0,0,0,0,0,0,0};
    #pragma unroll 4
    for (int c = 0; c < C; c++) {
        float wo = Wo[c*HID + t];
        #pragma unroll
        for (int j = 0; j < 8; j++) acc[j] += Wrs[j][c] * wo;
    }
    #pragma unroll
    for (int j = 0; j < 8; j++) g_E[ax][(d0 + j)*HID + t] = acc[j];
    if (t < 8) {
        float e = 0.f;
        for (int c = 0; c < C; c++) e += Wrs[t][c] * bo[c];
        g_e[ax][d0 + t] = e;
    }
}

// ---------------- K1: per-pixel channel norms -> w ---------------------------
__global__ void k_norm(const float* __restrict__ x) {
    int b = blockIdx.x / 160, n = blockIdx.x % 160, m = threadIdx.x;
    const float* xp = x + ((size_t)b*C*160 + n)*160 + m;
    float ss = 0.f;
    #pragma unroll 8
    for (int c = 0; c < C; c++) { float v = xp[(size_t)c*25600]; ss += v*v; }
    g_w[(b*160 + n)*160 + m] = SQRTC / fmaxf(sqrtf(ss), 1e-12f);
}

// ---------------- K2: one pass over x -> row_ft, col_ft, vbr, vbc -----------
__global__ void k_reduce(const float* __restrict__ x, const float* __restrict__ gv) {
    int b = blockIdx.x / C, c = blockIdx.x % C;
    int lane = threadIdx.x & 31, warp = threadIdx.x >> 5;   // 8 warps
    const float* xp = x + (size_t)(b*C + c)*25600;
    const float* wp = g_w + b*25600;
    float gvc = gv[c];
    float colp[5] = {0,0,0,0,0}, vrp[5] = {0,0,0,0,0};
    for (int i = 0; i < 20; i++) {
        int n = warp*20 + i;
        float rs = 0.f, vcs = 0.f;
        #pragma unroll
        for (int mc = 0; mc < 5; mc++) {
            int m = mc*32 + lane;
            float v  = xp[n*160 + m];
            float wv = wp[n*160 + m];
            rs += v; vcs += v*wv;
            colp[mc] += v; vrp[mc] += v*wv;
        }
        #pragma unroll
        for (int o = 16; o; o >>= 1) {
            rs  += __shfl_xor_sync(0xffffffffu, rs,  o);
            vcs += __shfl_xor_sync(0xffffffffu, vcs, o);
        }
        if (!lane) {
            g_rowft[(b*C + c)*160 + n] = rs * (1.0f/160.0f);
            g_vbc  [(b*C + c)*160 + n] = gvc * vcs;
        }
    }
    __shared__ float scol[8][160], svr[8][160];
    #pragma unroll
    for (int mc = 0; mc < 5; mc++) {
        scol[warp][mc*32 + lane] = colp[mc];
        svr [warp][mc*32 + lane] = vrp[mc];
    }
    __syncthreads();
    if (threadIdx.x < 160) {
        int m = threadIdx.x;
        float cs = 0.f, vr = 0.f;
        #pragma unroll
        for (int w2 = 0; w2 < 8; w2++) { cs += scol[w2][m]; vr += svr[w2][m]; }
        g_colft[(b*C + c)*160 + m] = cs * (1.0f/160.0f);
        g_vbr  [(b*C + c)*160 + m] = gvc * vr;
    }
}

// ---------------- K3: six (128 x 640, K=192) projections, norms inline ------
// which: 0=Q_row 1=K_row 2=V_row 3=Q_col 4=K_col 5=V_col
__global__ void __launch_bounds__(256) k_proj(
        const float* __restrict__ Wq, const float* __restrict__ Wk,
        const float* __restrict__ Wv, const float* __restrict__ gq,
        const float* __restrict__ gk) {
    int which = blockIdx.y;
    int p0 = blockIdx.x * 32;
    int b = p0 / 160, q0 = p0 % 160;
    const float *src, *W, *gvec = 0;
    float* out; float factor = 1.f;
    switch (which) {
        case 0: src=g_rowft; W=Wq; gvec=gq; out=g_q[0];  factor=SCALE*SQRTC; break;
        case 1: src=g_colft; W=Wk; gvec=gk; out=g_k[0];  factor=SQRTC;       break;
        case 2: src=g_vbr;   W=Wv;          out=g_vs[0];                     break;
        case 3: src=g_colft; W=Wq; gvec=gq; out=g_q[1];  factor=SCALE*SQRTC; break;
        case 4: src=g_rowft; W=Wk; gvec=gk; out=g_k[1];  factor=SQRTC;       break;
        default:src=g_vbc;   W=Wv;          out=g_vs[1];                     break;
    }
    __shared__ __align__(16) float Xs[192][36];
    __shared__ __align__(16) float Wsm[32][132];
    __shared__ float red[8][32];
    __shared__ float fs[32];
    int t = threadIdx.x;
    // load raw X tile (192 x 32)
    for (int idx = t; idx < 192*32; idx += 256) {
        int c = idx >> 5, pp = idx & 31;
        Xs[c][pp] = src[(b*C + c)*160 + q0 + pp];
    }
    __syncthreads();
    // per-position channel norms (only Q/K need them)
    if (gvec) {
        int p = t & 31, cg = t >> 5;
        float ssp = 0.f;
        #pragma unroll 4
        for (int c = cg; c < 192; c += 8) { float v = Xs[c][p]; ssp += v*v; }
        red[cg][p] = ssp;
    }
    __syncthreads();
    if (t < 32) {
        if (gvec) {
            float ss = 0.f;
            #pragma unroll
            for (int j = 0; j < 8; j++) ss += red[j][t];
            fs[t] = factor / fmaxf(sqrtf(ss), 1e-12f);
        } else fs[t] = 1.f;
    }

    int d0 = (t & 31) * 4, pl = (t >> 5) * 4;
    float4 acc0 = {0,0,0,0}, acc1 = {0,0,0,0}, acc2 = {0,0,0,0}, acc3 = {0,0,0,0};
    for (int c0 = 0; c0 < 192; c0 += 32) {
        __syncthreads();
        for (int idx = t; idx < 32*128; idx += 256) {
            int dim = idx >> 5, k = idx & 31;
            float wv = W[dim*C + c0 + k];
            if (gvec) wv *= gvec[c0 + k];
            Wsm[k][dim] = wv;
        }
        __syncthreads();
        #pragma unroll
        for (int k = 0; k < 32; k++) {
            float4 wv = *(const float4*)&Wsm[k][d0];
            float4 xv = *(const float4*)&Xs[c0 + k][pl];
            acc0.x += wv.x*xv.x; acc0.y += wv.y*xv.x; acc0.z += wv.z*xv.x; acc0.w += wv.w*xv.x;
            acc1.x += wv.x*xv.y; acc1.y += wv.y*xv.y; acc1.z += wv.z*xv.y; acc1.w += wv.w*xv.y;
            acc2.x += wv.x*xv.z; acc2.y += wv.y*xv.z; acc2.z += wv.z*xv.z; acc2.w += wv.w*xv.z;
            acc3.x += wv.x*xv.w; acc3.y += wv.y*xv.w; acc3.z += wv.z*xv.w; acc3.w += wv.w*xv.w;
        }
    }
    int h = d0 >> 5, dd = d0 & 31;
    float4 accs[4] = {acc0, acc1, acc2, acc3};
    #pragma unroll
    for (int pg = 0; pg < 4; pg++) {
        float f = fs[pl + pg];
        float4 v = accs[pg];
        v.x *= f; v.y *= f; v.z *= f; v.w *= f;
        *(float4*)&out[((b*HEADS + h)*160 + q0 + pl + pg)*DH + dd] = v;
    }
}

// ---------------- K4: attention with memory KV -------------------------------
__global__ void k_attn(const float* __restrict__ memkv) {
    int axial = blockIdx.z, bh = blockIdx.y, qt = blockIdx.x;
    int h = bh & 3;
    const float* Q = g_q [axial] + (bh*160 + qt*32)*DH;
    const float* K = g_k [axial] + bh*160*DH;
    const float* V = g_vs[axial] + bh*160*DH;
    __shared__ float Ks[164][33];
    __shared__ float Qs[32][33];
    __shared__ float S [32][168];
    __shared__ float invZ[32];
    int tid = threadIdx.x;
    for (int idx = tid; idx < 160*32; idx += 256) Ks[idx >> 5][idx & 31] = K[idx];
    for (int idx = tid; idx < 4*32;   idx += 256) {
        int j = idx >> 5, d = idx & 31;
        Ks[160 + j][d] = memkv[(h*NMEM + j)*DH + d];
    }
    for (int idx = tid; idx < 32*32; idx += 256) Qs[idx >> 5][idx & 31] = Q[idx];
    __syncthreads();
    for (int idx = tid; idx < 32*164; idx += 256) {
        int qi = idx / 164, k = idx - qi*164;
        float s = 0.f;
        #pragma unroll
        for (int d = 0; d < 32; d++) s += Qs[qi][d] * Ks[k][d];
        S[qi][k] = s;
    }
    __syncthreads();
    int warp = tid >> 5, lane = tid & 31;
    for (int qi = warp; qi < 32; qi += 8) {
        float mx = -1e30f;
        for (int k = lane; k < 164; k += 32) mx = fmaxf(mx, S[qi][k]);
        #pragma unroll
        for (int o = 16; o; o >>= 1) mx = fmaxf(mx, __shfl_xor_sync(0xffffffffu, mx, o));
        float z = 0.f;
        for (int k = lane; k < 164; k += 32) {
            float e = __expf(S[qi][k] - mx);
            S[qi][k] = e;
            z += (k < 160 ? 160.0f : 1.0f) * e;   // rep = N = M = 160
        }
        #pragma unroll
        for (int o = 16; o; o >>= 1) z += __shfl_xor_sync(0xffffffffu, z, o);
        if (!lane) invZ[qi] = 1.0f / z;
    }
    __syncthreads();
    int d = tid & 31, q0 = tid >> 5;
    float acc[4] = {0.f, 0.f, 0.f, 0.f};
    for (int k = 0; k < 160; k++) {
        float vv = V[k*DH + d];
        #pragma unroll
        for (int i = 0; i < 4; i++) acc[i] += S[q0 + 8*i][k] * vv;
    }
    const float* memv = memkv + HEADS*NMEM*DH;
    #pragma unroll
    for (int j = 0; j < 4; j++) {
        float vv = memv[(h*NMEM + j)*DH + d];
        #pragma unroll
        for (int i = 0; i < 4; i++) acc[i] += S[q0 + 8*i][160 + j] * vv;
    }
    // transpose through Qs (dead after S compute) so global store is coalesced
    #pragma unroll
    for (int i = 0; i < 4; i++) {
        int qi = q0 + 8*i;
        Qs[d][qi] = acc[i] * invZ[qi];
    }
    __syncthreads();
    float* outp = g_hoT[axial] + bh*32*160 + qt*32;
    #pragma unroll
    for (int r = 0; r < 4; r++) {
        int dd = r*8 + (tid >> 5);
        int qq = tid & 31;
        outp[dd*160 + qq] = Qs[dd][qq];
    }
}

// ---------------- K5: fused E-GEMM + broadcast write -------------------------
__global__ void k_final(float* __restrict__ out) {
    int d0 = blockIdx.x * 4, b = blockIdx.y;
    __shared__ float Es[2][4][128];
    __shared__ __align__(16) float Frs[4][160], Fcs[4][160];
    int t = threadIdx.x;  // 160
    for (int idx = t; idx < 2*4*128; idx += 160) {
        int ax = idx >> 9, dl = (idx >> 7) & 3, hd = idx & 127;
        Es[ax][dl][hd] = g_E[ax][(d0 + dl)*HID + hd];
    }
    __syncthreads();
    int pos = t;
    const float* hr = g_hoT[0] + b*HID*160 + pos;
    const float* hc = g_hoT[1] + b*HID*160 + pos;
    float fr[4] = {0,0,0,0}, fc[4] = {0,0,0,0};
    #pragma unroll 4
    for (int hid = 0; hid < HID; hid++) {
        float a  = hr[hid*160];
        float bb = hc[hid*160];
        #pragma unroll
        for (int dl = 0; dl < 4; dl++) {
            fr[dl] += Es[0][dl][hid] * a;
            fc[dl] += Es[1][dl][hid] * bb;
        }
    }
    #pragma unroll
    for (int dl = 0; dl < 4; dl++) {
        Frs[dl][pos] = fr[dl] + g_e[0][d0 + dl];
        Fcs[dl][pos] = fc[dl] + g_e[1][d0 + dl];
    }
    __syncthreads();
    int m4 = t % 40, nb = t / 40;  // nb in [0,4)
    #pragma unroll
    for (int dl = 0; dl < 4; dl++) {
        float4 cv = *(const float4*)&Fcs[dl][m4*4];
        float* op = out + ((size_t)(b*C + d0 + dl)*160)*160 + m4*4;
        #pragma unroll 8
        for (int i = 0; i < 40; i++) {
            int n = nb + 4*i;
            float r = Frs[dl][n];
            float4 v = {r + cv.x, r + cv.y, r + cv.z, r + cv.w};
            *(float4*)&op[n*160] = v;
        }
    }
}

// ---------------- launch ------------------------------------------------------
extern "C" void kernel_launch(void* const* d_in, const int* in_sizes, int n_in,
                              void* d_out, int out_size) {
    const float* x     = (const float*)d_in[0];
    const float* gq    = (const float*)d_in[1];
    const float* gk    = (const float*)d_in[2];
    const float* gv    = (const float*)d_in[3];
    const float* Wq    = (const float*)d_in[4];
    const float* Wk    = (const float*)d_in[5];
    const float* Wv    = (const float*)d_in[6];
    const float* memkv = (const float*)d_in[7];
    const float* Wo    = (const float*)d_in[8];
    const float* bo    = (const float*)d_in[9];
    const float* Wr    = (const float*)d_in[10];
    float* out = (float*)d_out;

    k_fold  <<<dim3(2, 24), 128>>>(Wr, Wo, bo);
    k_norm  <<<B*160, 160>>>(x);
    k_reduce<<<B*C, 256>>>(x, gv);
    k_proj  <<<dim3(20, 6), 256>>>(Wq, Wk, Wv, gq, gk);
    k_attn  <<<dim3(5, 16, 2), 256>>>(memkv);
    k_final <<<dim3(48, 4), 160>>>(out);
}

// round 3
// speedup vs baseline: 1.6375x; 1.3132x over previous
#include <cuda_runtime.h>
#include <math.h>

#define B 4
#define C 192
#define HEADS 4
#define DH 32
#define HID 128
#define NMEM 4
#define QT 16
#define SQRTC 13.856406460551018f   /* sqrt(192) */
#define SCALE 0.17677669529663687f  /* 32^-0.5 */

// ---------------- scratch ----------------------------------------------------
__device__ float g_w[B*160*160];
__device__ float g_rowft[B*C*160];
__device__ float g_colft[B*C*160];
__device__ float g_vbr[B*C*160];
__device__ float g_vbc[B*C*160];
__device__ float g_qp[2][2][B*HEADS*160*DH];   // [ksplit][axial]
__device__ float g_kp[2][2][B*HEADS*160*DH];
__device__ float g_vp[2][2][B*HEADS*160*DH];
__device__ float g_hoT[2][B*HID*160];          // [(b*128+hid)*160 + pos]

// ---------------- K1: per-pixel channel norms -> w ---------------------------
__global__ void k_norm(const float* __restrict__ x) {
    int b = blockIdx.x / 160, n = blockIdx.x % 160, m = threadIdx.x;
    const float* xp = x + ((size_t)b*C*160 + n)*160 + m;
    float ss = 0.f;
    #pragma unroll 8
    for (int c = 0; c < C; c++) { float v = xp[(size_t)c*25600]; ss += v*v; }
    g_w[(b*160 + n)*160 + m] = SQRTC / fmaxf(sqrtf(ss), 1e-12f);
}

// ---------------- K2: one pass over x -> row_ft, col_ft, vbr, vbc ------------
__global__ void k_reduce(const float* __restrict__ x, const float* __restrict__ gv) {
    int b = blockIdx.x / C, c = blockIdx.x % C;
    int lane = threadIdx.x & 31, warp = threadIdx.x >> 5;   // 8 warps
    const float* xp = x + (size_t)(b*C + c)*25600;
    const float* wp = g_w + b*25600;
    float gvc = gv[c];
    float colp[5] = {0,0,0,0,0}, vrp[5] = {0,0,0,0,0};
    for (int i = 0; i < 20; i++) {
        int n = warp*20 + i;
        float rs = 0.f, vcs = 0.f;
        #pragma unroll
        for (int mc = 0; mc < 5; mc++) {
            int m = mc*32 + lane;
            float v  = xp[n*160 + m];
            float wv = wp[n*160 + m];
            rs += v; vcs += v*wv;
            colp[mc] += v; vrp[mc] += v*wv;
        }
        #pragma unroll
        for (int o = 16; o; o >>= 1) {
            rs  += __shfl_xor_sync(0xffffffffu, rs,  o);
            vcs += __shfl_xor_sync(0xffffffffu, vcs, o);
        }
        if (!lane) {
            g_rowft[(b*C + c)*160 + n] = rs * (1.0f/160.0f);
            g_vbc  [(b*C + c)*160 + n] = gvc * vcs;
        }
    }
    __shared__ float scol[8][160], svr[8][160];
    #pragma unroll
    for (int mc = 0; mc < 5; mc++) {
        scol[warp][mc*32 + lane] = colp[mc];
        svr [warp][mc*32 + lane] = vrp[mc];
    }
    __syncthreads();
    if (threadIdx.x < 160) {
        int m = threadIdx.x;
        float cs = 0.f, vr = 0.f;
        #pragma unroll
        for (int w2 = 0; w2 < 8; w2++) { cs += scol[w2][m]; vr += svr[w2][m]; }
        g_colft[(b*C + c)*160 + m] = cs * (1.0f/160.0f);
        g_vbr  [(b*C + c)*160 + m] = gvc * vr;
    }
}

// ---------------- K3: projections, split-K=2, norms inline -------------------
__global__ void __launch_bounds__(256) k_proj(
        const float* __restrict__ Wq, const float* __restrict__ Wk,
        const float* __restrict__ Wv, const float* __restrict__ gq,
        const float* __restrict__ gk) {
    int which = blockIdx.y, z = blockIdx.z;
    int p0 = blockIdx.x * 32;
    int b = p0 / 160, q0 = p0 % 160;
    const float *src, *W, *gvec = 0;
    float* out; float factor = 1.f;
    switch (which) {
        case 0: src=g_rowft; W=Wq; gvec=gq; out=g_qp[z][0]; factor=SCALE*SQRTC; break;
        case 1: src=g_colft; W=Wk; gvec=gk; out=g_kp[z][0]; factor=SQRTC;       break;
        case 2: src=g_vbr;   W=Wv;          out=g_vp[z][0];                     break;
        case 3: src=g_colft; W=Wq; gvec=gq; out=g_qp[z][1]; factor=SCALE*SQRTC; break;
        case 4: src=g_rowft; W=Wk; gvec=gk; out=g_kp[z][1]; factor=SQRTC;       break;
        default:src=g_vbc;   W=Wv;          out=g_vp[z][1];                     break;
    }
    __shared__ __align__(16) float Xs[192][36];
    __shared__ __align__(16) float Wsm[32][132];
    __shared__ float red[8][32];
    __shared__ float fs[32];
    int t = threadIdx.x;
    for (int idx = t; idx < 192*32; idx += 256) {
        int c = idx >> 5, pp = idx & 31;
        Xs[c][pp] = src[(b*C + c)*160 + q0 + pp];
    }
    __syncthreads();
    if (gvec) {
        int p = t & 31, cg = t >> 5;
        float ssp = 0.f;
        #pragma unroll 4
        for (int c = cg; c < 192; c += 8) { float v = Xs[c][p]; ssp += v*v; }
        red[cg][p] = ssp;
    }
    __syncthreads();
    if (t < 32) {
        if (gvec) {
            float ss = 0.f;
            #pragma unroll
            for (int j = 0; j < 8; j++) ss += red[j][t];
            fs[t] = factor / fmaxf(sqrtf(ss), 1e-12f);
        } else fs[t] = 1.f;
    }

    int d0 = (t & 31) * 4, pl = (t >> 5) * 4;
    float4 acc0 = {0,0,0,0}, acc1 = {0,0,0,0}, acc2 = {0,0,0,0}, acc3 = {0,0,0,0};
    int cbase = z * 96;
    for (int cc0 = 0; cc0 < 96; cc0 += 32) {
        int c0 = cbase + cc0;
        __syncthreads();
        for (int idx = t; idx < 32*128; idx += 256) {
            int dim = idx >> 5, k = idx & 31;
            float wv = W[dim*C + c0 + k];
            if (gvec) wv *= gvec[c0 + k];
            Wsm[k][dim] = wv;
        }
        __syncthreads();
        #pragma unroll
        for (int k = 0; k < 32; k++) {
            float4 wv = *(const float4*)&Wsm[k][d0];
            float4 xv = *(const float4*)&Xs[c0 + k][pl];
            acc0.x += wv.x*xv.x; acc0.y += wv.y*xv.x; acc0.z += wv.z*xv.x; acc0.w += wv.w*xv.x;
            acc1.x += wv.x*xv.y; acc1.y += wv.y*xv.y; acc1.z += wv.z*xv.y; acc1.w += wv.w*xv.y;
            acc2.x += wv.x*xv.z; acc2.y += wv.y*xv.z; acc2.z += wv.z*xv.z; acc2.w += wv.w*xv.z;
            acc3.x += wv.x*xv.w; acc3.y += wv.y*xv.w; acc3.z += wv.z*xv.w; acc3.w += wv.w*xv.w;
        }
    }
    int h = d0 >> 5, dd = d0 & 31;
    float4 accs[4] = {acc0, acc1, acc2, acc3};
    #pragma unroll
    for (int pg = 0; pg < 4; pg++) {
        float f = fs[pl + pg];
        float4 v = accs[pg];
        v.x *= f; v.y *= f; v.z *= f; v.w *= f;
        *(float4*)&out[((b*HEADS + h)*160 + q0 + pl + pg)*DH + dd] = v;
    }
}

// ---------------- K4: attention, 16-q tiles, warp-owned rows ------------------
__global__ void __launch_bounds__(256) k_attn(const float* __restrict__ memkv) {
    int axial = blockIdx.z, bh = blockIdx.y, qt = blockIdx.x;
    int h = bh & 3, b = bh >> 2;
    const float* K0 = g_kp[0][axial] + bh*160*DH;
    const float* K1 = g_kp[1][axial] + bh*160*DH;
    const float* Q0 = g_qp[0][axial] + (bh*160 + qt*QT)*DH;
    const float* Q1 = g_qp[1][axial] + (bh*160 + qt*QT)*DH;
    const float* V0 = g_vp[0][axial] + bh*160*DH;
    const float* V1 = g_vp[1][axial] + bh*160*DH;

    __shared__ __align__(16) float KV[164][36];   // Ks -> Vs -> Ot (flat)
    __shared__ __align__(16) float S[QT][164];
    __shared__ __align__(16) float Qsm[QT][36];
    __shared__ float invZ[QT];

    int tid = threadIdx.x, warp = tid >> 5, lane = tid & 31;
    for (int idx = tid; idx < 160*32; idx += 256)
        KV[idx >> 5][idx & 31] = K0[idx] + K1[idx];
    if (tid < 128)
        KV[160 + (tid >> 5)][tid & 31] = memkv[(h*NMEM + (tid >> 5))*DH + (tid & 31)];
    for (int idx = tid; idx < QT*32; idx += 256)
        Qsm[idx >> 5][idx & 31] = Q0[idx] + Q1[idx];
    __syncthreads();

    int qr = warp*2;
    float s0[6], s1[6];
    #pragma unroll
    for (int j = 0; j < 6; j++) {
        int k = lane + 32*j;
        float a0 = 0.f, a1 = 0.f;
        if (k < 164) {
            #pragma unroll
            for (int d4 = 0; d4 < 8; d4++) {
                float4 kv = *(const float4*)&KV[k][d4*4];
                float4 qa = *(const float4*)&Qsm[qr][d4*4];
                float4 qb = *(const float4*)&Qsm[qr+1][d4*4];
                a0 += qa.x*kv.x + qa.y*kv.y + qa.z*kv.z + qa.w*kv.w;
                a1 += qb.x*kv.x + qb.y*kv.y + qb.z*kv.z + qb.w*kv.w;
            }
        }
        s0[j] = a0; s1[j] = a1;
    }
    float mx0 = -1e30f, mx1 = -1e30f;
    #pragma unroll
    for (int j = 0; j < 6; j++) {
        if (lane + 32*j < 164) { mx0 = fmaxf(mx0, s0[j]); mx1 = fmaxf(mx1, s1[j]); }
    }
    #pragma unroll
    for (int o = 16; o; o >>= 1) {
        mx0 = fmaxf(mx0, __shfl_xor_sync(0xffffffffu, mx0, o));
        mx1 = fmaxf(mx1, __shfl_xor_sync(0xffffffffu, mx1, o));
    }
    float z0 = 0.f, z1 = 0.f;
    #pragma unroll
    for (int j = 0; j < 6; j++) {
        int k = lane + 32*j;
        if (k < 164) {
            float w = (k < 160) ? 160.0f : 1.0f;
            float e0 = __expf(s0[j] - mx0), e1 = __expf(s1[j] - mx1);
            S[qr][k] = e0; S[qr+1][k] = e1;
            z0 += w*e0; z1 += w*e1;
        }
    }
    #pragma unroll
    for (int o = 16; o; o >>= 1) {
        z0 += __shfl_xor_sync(0xffffffffu, z0, o);
        z1 += __shfl_xor_sync(0xffffffffu, z1, o);
    }
    if (!lane) { invZ[qr] = 1.0f / z0; invZ[qr+1] = 1.0f / z1; }
    __syncthreads();
    // V into KV space (Ks dead)
    for (int idx = tid; idx < 160*32; idx += 256)
        KV[idx >> 5][idx & 31] = V0[idx] + V1[idx];
    if (tid < 128)
        KV[160 + (tid >> 5)][tid & 31] =
            memkv[HEADS*NMEM*DH + (h*NMEM + (tid >> 5))*DH + (tid & 31)];
    __syncthreads();
    float acc0 = 0.f, acc1 = 0.f;
    #pragma unroll 4
    for (int k4 = 0; k4 < 41; k4++) {
        float4 e0 = *(const float4*)&S[qr][k4*4];
        float4 e1 = *(const float4*)&S[qr+1][k4*4];
        float v0 = KV[k4*4+0][lane], v1 = KV[k4*4+1][lane];
        float v2 = KV[k4*4+2][lane], v3 = KV[k4*4+3][lane];
        acc0 += e0.x*v0 + e0.y*v1 + e0.z*v2 + e0.w*v3;
        acc1 += e1.x*v0 + e1.y*v1 + e1.z*v2 + e1.w*v3;
    }
    float o0 = acc0 * invZ[qr], o1 = acc1 * invZ[qr+1];
    __syncthreads();                 // all done reading KV(V)
    float* Ob = &KV[0][0];
    Ob[lane*17 + qr]     = o0;       // lane = d
    Ob[lane*17 + qr + 1] = o1;
    __syncthreads();
    float* outp = g_hoT[axial] + (size_t)(b*HID + h*DH)*160 + qt*QT;
    for (int idx = tid; idx < 32*QT; idx += 256) {
        int d = idx >> 4, q = idx & 15;
        outp[d*160 + q] = Ob[d*17 + q];
    }
}

// ---------------- K5: fold + E-GEMM + broadcast write ------------------------
__global__ void k_final(const float* __restrict__ Wr, const float* __restrict__ Wo,
                        const float* __restrict__ bo, float* __restrict__ out) {
    int d0 = blockIdx.x * 2, b = blockIdx.y;
    __shared__ float Wr4[4][192];                 // r = ax*2+dl
    __shared__ float Es[4][128];
    __shared__ float eb[4];
    __shared__ __align__(16) float Frs[2][160], Fcs[2][160];
    int t = threadIdx.x;  // 160
    for (int idx = t; idx < 4*192; idx += 160) {
        int r = idx / 192, c = idx % 192;
        Wr4[r][c] = Wr[(d0 + (r & 1))*2*C + (r >> 1)*C + c];
    }
    __syncthreads();
    if (t < 128) {
        float a0 = 0, a1 = 0, a2 = 0, a3 = 0;
        #pragma unroll 4
        for (int c = 0; c < 192; c++) {
            float wo = Wo[c*HID + t];
            a0 += Wr4[0][c]*wo; a1 += Wr4[1][c]*wo;
            a2 += Wr4[2][c]*wo; a3 += Wr4[3][c]*wo;
        }
        Es[0][t] = a0; Es[1][t] = a1; Es[2][t] = a2; Es[3][t] = a3;
    } else if (t < 132) {
        int r = t - 128; float e = 0.f;
        for (int c = 0; c < 192; c++) e += Wr4[r][c] * bo[c];
        eb[r] = e;
    }
    __syncthreads();
    {
        const float* hr = g_hoT[0] + (size_t)b*HID*160 + t;
        const float* hc = g_hoT[1] + (size_t)b*HID*160 + t;
        float fr0 = 0, fr1 = 0, fc0 = 0, fc1 = 0;
        #pragma unroll 4
        for (int hid = 0; hid < HID; hid++) {
            float a  = hr[hid*160];
            float bb = hc[hid*160];
            fr0 += Es[0][hid]*a;  fr1 += Es[1][hid]*a;
            fc0 += Es[2][hid]*bb; fc1 += Es[3][hid]*bb;
        }
        Frs[0][t] = fr0 + eb[0]; Frs[1][t] = fr1 + eb[1];
        Fcs[0][t] = fc0 + eb[2]; Fcs[1][t] = fc1 + eb[3];
    }
    __syncthreads();
    int m4 = t % 40, nb = t / 40;
    #pragma unroll
    for (int dl = 0; dl < 2; dl++) {
        float4 cv = *(const float4*)&Fcs[dl][m4*4];
        float* op = out + ((size_t)(b*C + d0 + dl)*160)*160 + m4*4;
        #pragma unroll 8
        for (int i = 0; i < 40; i++) {
            int n = nb + 4*i;
            float r = Frs[dl][n];
            float4 v = {r + cv.x, r + cv.y, r + cv.z, r + cv.w};
            *(float4*)&op[(size_t)n*160] = v;
        }
    }
}

// ---------------- launch ------------------------------------------------------
extern "C" void kernel_launch(void* const* d_in, const int* in_sizes, int n_in,
                              void* d_out, int out_size) {
    const float* x     = (const float*)d_in[0];
    const float* gq    = (const float*)d_in[1];
    const float* gk    = (const float*)d_in[2];
    const float* gv    = (const float*)d_in[3];
    const float* Wq    = (const float*)d_in[4];
    const float* Wk    = (const float*)d_in[5];
    const float* Wv    = (const float*)d_in[6];
    const float* memkv = (const float*)d_in[7];
    const float* Wo    = (const float*)d_in[8];
    const float* bo    = (const float*)d_in[9];
    const float* Wr    = (const float*)d_in[10];
    float* out = (float*)d_out;

    k_norm  <<<B*160, 160>>>(x);
    k_reduce<<<B*C, 256>>>(x, gv);
    k_proj  <<<dim3(20, 6, 2), 256>>>(Wq, Wk, Wv, gq, gk);
    k_attn  <<<dim3(10, 16, 2), 256>>>(memkv);
    k_final <<<dim3(96, 4), 160>>>(Wr, Wo, bo, out);
}